// round 1
// baseline (speedup 1.0000x reference)
#include <cuda_runtime.h>
#include <cstdint>

// Problem constants (fixed shapes from setup_inputs)
#define TS   2048    // tokens S = B*T
#define HD   1024    // hidden
#define FFD  1024    // ff
#define NE   16      // experts
#define NK   4       // top-k
#define AST  36      // A smem row stride (floats), conflict-free
#define BST  72      // B smem row stride (floats), conflict-free

// ---------------- scratch (device globals; no allocs allowed) ----------------
__device__ int   g_counts[NE];
__device__ int   g_tok[NE][TS];
__device__ float g_gate[NE][TS];
__device__ float g_imp[NE];
__device__ int   g_loadcnt[NK];
__device__ float g_act[(size_t)NE * TS * FFD];   // 134 MB

// ---------------- helpers ----------------
__device__ __forceinline__ uint32_t tf32u(float x) {
    uint32_t u; asm("cvt.rna.tf32.f32 %0, %1;" : "=r"(u) : "f"(x)); return u;
}
__device__ __forceinline__ void mma_tf32(float d[4], const uint32_t a[4], const uint32_t b[2]) {
    asm volatile(
        "mma.sync.aligned.m16n8k8.row.col.f32.tf32.tf32.f32 "
        "{%0,%1,%2,%3}, {%4,%5,%6,%7}, {%8,%9}, {%0,%1,%2,%3};"
        : "+f"(d[0]), "+f"(d[1]), "+f"(d[2]), "+f"(d[3])
        : "r"(a[0]), "r"(a[1]), "r"(a[2]), "r"(a[3]), "r"(b[0]), "r"(b[1]));
}
__device__ __forceinline__ uint32_t s2u(const void* p) {
    return (uint32_t)__cvta_generic_to_shared(p);
}
__device__ __forceinline__ void cpa16(uint32_t dst, const void* src) {
    asm volatile("cp.async.ca.shared.global [%0], [%1], 16;" :: "r"(dst), "l"(src));
}
__device__ __forceinline__ void cpa_commit() { asm volatile("cp.async.commit_group;"); }
__device__ __forceinline__ void cpa_wait0()  { asm volatile("cp.async.wait_group 0;"); }
__device__ __forceinline__ void cpa_wait1()  { asm volatile("cp.async.wait_group 1;"); }

// ---------------- kernel 0: zero counters ----------------
__global__ void zero_kernel() {
    int t = threadIdx.x;
    if (t < NE) { g_counts[t] = 0; g_imp[t] = 0.f; }
    if (t < NK) g_loadcnt[t] = 0;
}

// ---------------- kernel 1: router + gating + aux stats + scatter ----------------
__global__ void router_kernel(const float* __restrict__ x,
                              const float* __restrict__ rw,
                              const float* __restrict__ rb) {
    __shared__ float xs[HD];
    __shared__ float lg[NE];
    const int s = blockIdx.x;
    const int tid = threadIdx.x;
    const float* xrow = x + (size_t)s * HD;
    for (int i = tid; i < HD / 4; i += 128)
        ((float4*)xs)[i] = ((const float4*)xrow)[i];
    __syncthreads();

    const int w = tid >> 5, lane = tid & 31;
    for (int e = w; e < NE; e += 4) {
        const float* r = rw + (size_t)e * HD;
        float p = 0.f;
        for (int i = lane; i < HD; i += 32) p += xs[i] * r[i];
        #pragma unroll
        for (int o = 16; o; o >>= 1) p += __shfl_xor_sync(0xFFFFFFFFu, p, o);
        if (lane == 0) lg[e] = p + rb[e];
    }
    __syncthreads();

    if (tid == 0) {
        float v[NE];
        #pragma unroll
        for (int e = 0; e < NE; e++) v[e] = lg[e];

        // top-4 (strict >, so ties pick lowest index — matches lax.top_k)
        int idx[NK]; float tv[NK]; bool used[NE];
        #pragma unroll
        for (int e = 0; e < NE; e++) used[e] = false;
        for (int k = 0; k < NK; k++) {
            int bi = 0; float bv = -3.0e38f;
            for (int e = 0; e < NE; e++)
                if (!used[e] && v[e] > bv) { bv = v[e]; bi = e; }
            used[bi] = true; idx[k] = bi; tv[k] = bv;
        }
        // softmax over top-4 values
        float w4[NK], den = 0.f, m = tv[0];
        for (int k = 0; k < NK; k++) { w4[k] = expf(tv[k] - m); den += w4[k]; }
        for (int k = 0; k < NK; k++) w4[k] /= den;

        // full softmax -> importance accumulation
        float mm = v[0];
        for (int e = 1; e < NE; e++) mm = fmaxf(mm, v[e]);
        float pr[NE], d2 = 0.f;
        for (int e = 0; e < NE; e++) { pr[e] = expf(v[e] - mm); d2 += pr[e]; }
        for (int e = 0; e < NE; e++) atomicAdd(&g_imp[e], pr[e] / d2);

        // load = one_hot(argmax over top-k *indices*, E)  (faithful to source)
        int jm = 0;
        for (int k = 1; k < NK; k++) if (idx[k] > idx[jm]) jm = k;
        atomicAdd(&g_loadcnt[jm], 1);

        // scatter token into its 4 expert lists
        for (int k = 0; k < NK; k++) {
            int e = idx[k];
            int slot = atomicAdd(&g_counts[e], 1);
            g_tok[e][slot]  = s;
            g_gate[e][slot] = w4[k];
        }
    }
}

// ---------------- kernel 2: grouped GEMM1 + clip/SiLU fusion ----------------
// act[e, m, f] = silu(clip(x_g @ Win[:, FFD+f] + b_g)) * clip(x_g @ Win[:, f] + b_u)
__global__ void gemm1_kernel(const float* __restrict__ x,
                             const float* __restrict__ Win,
                             const float* __restrict__ bin) {
    extern __shared__ float sm[];
    float* As = sm;                       // [2][64][AST]
    float* Bu = sm + 2 * 64 * AST;        // [2][32][BST]
    float* Bg = Bu + 2 * 32 * BST;        // [2][32][BST]
    __shared__ int toksm[64];

    const int e  = blockIdx.z;
    const int m0 = blockIdx.y * 64;
    const int n0 = blockIdx.x * 64;
    const int cnt = g_counts[e];
    if (m0 >= cnt) return;

    const int tid = threadIdx.x;
    if (tid < 64) {
        int r = m0 + tid;
        toksm[tid] = (r < cnt) ? g_tok[e][r] : 0;
    }
    __syncthreads();

    const uint32_t asb = s2u(As), bub = s2u(Bu), bgb = s2u(Bg);
    const float* Wb = Win + (size_t)e * HD * (2 * FFD);

    const int ar = tid >> 3, ac = (tid & 7) * 4;
    const int br = tid >> 4, bc = (tid & 15) * 4;

    auto issue = [&](int kc, int buf) {
        const int k0 = kc * 32;
        #pragma unroll
        for (int it = 0; it < 4; it++) {
            int r = it * 16 + ar;
            cpa16(asb + (uint32_t)((buf * 64 + r) * AST + ac) * 4,
                  x + (size_t)toksm[r] * HD + k0 + ac);
        }
        #pragma unroll
        for (int it = 0; it < 4; it++) {
            int r = it * 8 + br;
            const float* src = Wb + (size_t)(k0 + r) * (2 * FFD) + n0 + bc;
            cpa16(bub + (uint32_t)((buf * 32 + r) * BST + bc) * 4, src);
            cpa16(bgb + (uint32_t)((buf * 32 + r) * BST + bc) * 4, src + FFD);
        }
        cpa_commit();
    };

    float accU[2][4][4] = {}, accG[2][4][4] = {};
    const int wid = tid >> 5, lane = tid & 31;
    const int wm = wid >> 1, wn = wid & 1;
    const int gq = lane >> 2, tg = lane & 3;

    issue(0, 0);
    const int NKC = HD / 32;
    for (int kc = 0; kc < NKC; kc++) {
        const int buf = kc & 1;
        if (kc + 1 < NKC) { issue(kc + 1, buf ^ 1); cpa_wait1(); }
        else              { cpa_wait0(); }
        __syncthreads();

        const float* Ab  = As + (buf * 64 + wm * 32) * AST;
        const float* Bub = Bu + buf * 32 * BST + wn * 32;
        const float* Bgb = Bg + buf * 32 * BST + wn * 32;
        #pragma unroll
        for (int k8 = 0; k8 < 4; k8++) {
            const int kk = k8 * 8;
            uint32_t a[2][4];
            #pragma unroll
            for (int i = 0; i < 2; i++) {
                const float* ap = Ab + i * 16 * AST;
                a[i][0] = tf32u(ap[(gq    ) * AST + kk + tg    ]);
                a[i][1] = tf32u(ap[(gq + 8) * AST + kk + tg    ]);
                a[i][2] = tf32u(ap[(gq    ) * AST + kk + tg + 4]);
                a[i][3] = tf32u(ap[(gq + 8) * AST + kk + tg + 4]);
            }
            #pragma unroll
            for (int j = 0; j < 4; j++) {
                const int col = j * 8 + gq;
                uint32_t bu[2], bg[2];
                bu[0] = tf32u(Bub[(kk + tg    ) * BST + col]);
                bu[1] = tf32u(Bub[(kk + tg + 4) * BST + col]);
                bg[0] = tf32u(Bgb[(kk + tg    ) * BST + col]);
                bg[1] = tf32u(Bgb[(kk + tg + 4) * BST + col]);
                #pragma unroll
                for (int i = 0; i < 2; i++) {
                    mma_tf32(accU[i][j], a[i], bu);
                    mma_tf32(accG[i][j], a[i], bg);
                }
            }
        }
        __syncthreads();
    }

    // epilogue: bias + clip + SiLU, write act
    const int mlim = cnt - m0;
    const float* binU = bin + (size_t)e * 2 * FFD + n0;
    const float* binG = binU + FFD;
    #pragma unroll
    for (int i = 0; i < 2; i++) {
        #pragma unroll
        for (int j = 0; j < 4; j++) {
            #pragma unroll
            for (int q = 0; q < 4; q++) {
                const int r = wm * 32 + i * 16 + gq + ((q >= 2) ? 8 : 0);
                const int c = wn * 32 + j * 8 + tg * 2 + (q & 1);
                if (r < mlim) {
                    float up = accU[i][j][q] + binU[c];
                    float gt = accG[i][j][q] + binG[c];
                    up = fminf(fmaxf(up, -7.0f), 7.0f);
                    gt = fminf(fmaxf(gt, -7.0f), 7.0f);
                    float act = (gt / (1.0f + expf(-gt))) * up;
                    g_act[(size_t)(e * TS + m0 + r) * FFD + n0 + c] = act;
                }
            }
        }
    }
}

// ---------------- kernel 3: grouped GEMM2 + weighted scatter-add ----------------
__global__ void gemm2_kernel(const float* __restrict__ Wout,
                             const float* __restrict__ bout,
                             float* __restrict__ out) {
    __shared__ float As[2][64][AST];
    __shared__ float Bs[2][32][BST];
    __shared__ int   toksm[64];
    __shared__ float gsm[64];

    const int e  = blockIdx.z;
    const int m0 = blockIdx.y * 64;
    const int n0 = blockIdx.x * 64;
    const int cnt = g_counts[e];
    if (m0 >= cnt) return;

    const int tid = threadIdx.x;
    if (tid < 64) {
        int r = m0 + tid;
        toksm[tid] = (r < cnt) ? g_tok[e][r] : 0;
        gsm[tid]   = (r < cnt) ? g_gate[e][r] : 0.f;
    }
    __syncthreads();

    const uint32_t asb = s2u(As), bsb = s2u(Bs);
    const float* Wb   = Wout + (size_t)e * FFD * HD;
    const float* Arow = g_act + (size_t)(e * TS + m0) * FFD;

    const int ar = tid >> 3, ac = (tid & 7) * 4;
    const int br = tid >> 4, bc = (tid & 15) * 4;

    auto issue = [&](int kc, int buf) {
        const int k0 = kc * 32;
        #pragma unroll
        for (int it = 0; it < 4; it++) {
            int r = it * 16 + ar;
            cpa16(asb + (uint32_t)((buf * 64 + r) * AST + ac) * 4,
                  Arow + (size_t)r * FFD + k0 + ac);
        }
        #pragma unroll
        for (int it = 0; it < 4; it++) {
            int r = it * 8 + br;
            cpa16(bsb + (uint32_t)((buf * 32 + r) * BST + bc) * 4,
                  Wb + (size_t)(k0 + r) * HD + n0 + bc);
        }
        cpa_commit();
    };

    float acc[2][4][4] = {};
    const int wid = tid >> 5, lane = tid & 31;
    const int wm = wid >> 1, wn = wid & 1;
    const int gq = lane >> 2, tg = lane & 3;

    issue(0, 0);
    const int NKC = FFD / 32;
    for (int kc = 0; kc < NKC; kc++) {
        const int buf = kc & 1;
        if (kc + 1 < NKC) { issue(kc + 1, buf ^ 1); cpa_wait1(); }
        else              { cpa_wait0(); }
        __syncthreads();

        const float* Ab = &As[buf][wm * 32][0];
        const float* Bb = &Bs[buf][0][wn * 32];
        #pragma unroll
        for (int k8 = 0; k8 < 4; k8++) {
            const int kk = k8 * 8;
            uint32_t a[2][4];
            #pragma unroll
            for (int i = 0; i < 2; i++) {
                const float* ap = Ab + i * 16 * AST;
                a[i][0] = tf32u(ap[(gq    ) * AST + kk + tg    ]);
                a[i][1] = tf32u(ap[(gq + 8) * AST + kk + tg    ]);
                a[i][2] = tf32u(ap[(gq    ) * AST + kk + tg + 4]);
                a[i][3] = tf32u(ap[(gq + 8) * AST + kk + tg + 4]);
            }
            #pragma unroll
            for (int j = 0; j < 4; j++) {
                const int col = j * 8 + gq;
                uint32_t b[2];
                b[0] = tf32u(Bb[(kk + tg    ) * BST + col]);
                b[1] = tf32u(Bb[(kk + tg + 4) * BST + col]);
                #pragma unroll
                for (int i = 0; i < 2; i++)
                    mma_tf32(acc[i][j], a[i], b);
            }
        }
        __syncthreads();
    }

    const int mlim = cnt - m0;
    const float* bo = bout + (size_t)e * HD + n0;
    #pragma unroll
    for (int i = 0; i < 2; i++) {
        #pragma unroll
        for (int j = 0; j < 4; j++) {
            #pragma unroll
            for (int q = 0; q < 4; q++) {
                const int r = wm * 32 + i * 16 + gq + ((q >= 2) ? 8 : 0);
                const int c = wn * 32 + j * 8 + tg * 2 + (q & 1);
                if (r < mlim) {
                    float val = acc[i][j][q] + bo[c];
                    atomicAdd(&out[(size_t)toksm[r] * HD + n0 + c], gsm[r] * val);
                }
            }
        }
    }
}

// ---------------- kernel 4: aux loss scalar ----------------
__global__ void aux_kernel(float* __restrict__ out, int out_size) {
    if (out_size > TS * HD) {
        float a = 0.f;
        #pragma unroll
        for (int j = 0; j < NK; j++)
            a += (g_imp[j] / (float)TS) * ((float)g_loadcnt[j] / (float)TS);
        out[TS * HD] = 0.02f * (float)NE * a;
    }
}

// ---------------- launcher ----------------
extern "C" void kernel_launch(void* const* d_in, const int* in_sizes, int n_in,
                              void* d_out, int out_size) {
    const float* x    = (const float*)d_in[0];
    const float* Win  = (const float*)d_in[1];
    const float* bin  = (const float*)d_in[2];
    const float* Wout = (const float*)d_in[3];
    const float* bout = (const float*)d_in[4];
    const float* rw   = (const float*)d_in[5];
    const float* rb   = (const float*)d_in[6];
    float* out = (float*)d_out;

    const int g1_smem = (2 * 64 * AST + 2 * 2 * 32 * BST) * 4;  // 55296 B
    cudaFuncSetAttribute(gemm1_kernel, cudaFuncAttributeMaxDynamicSharedMemorySize, g1_smem);

    cudaMemsetAsync(d_out, 0, (size_t)out_size * sizeof(float));
    zero_kernel<<<1, 32>>>();
    router_kernel<<<TS, 128>>>(x, rw, rb);
    gemm1_kernel<<<dim3(FFD / 64, TS / 64, NE), 128, g1_smem>>>(x, Win, bin);
    gemm2_kernel<<<dim3(HD / 64, TS / 64, NE), 128>>>(Wout, bout, out);
    aux_kernel<<<1, 1>>>(out, out_size);
}

// round 2
// speedup vs baseline: 1.0044x; 1.0044x over previous
#include <cuda_runtime.h>
#include <cstdint>

// Problem constants (fixed shapes from setup_inputs)
#define TS   2048    // tokens S = B*T
#define HD   1024    // hidden
#define FFD  1024    // ff
#define NE   16      // experts
#define NK   4       // top-k
#define AST  36      // A smem row stride (floats), conflict-free
#define BST  72      // B smem row stride (floats), conflict-free

// ---------------- scratch (device globals; no allocs allowed) ----------------
__device__ int   g_counts[NE];
__device__ int   g_tok[NE][TS];
__device__ float g_gate[NE][TS];
__device__ float g_imp[NE];
__device__ int   g_loadcnt[NK];
__device__ float g_act[(size_t)NE * TS * FFD];   // 134 MB

// ---------------- helpers ----------------
__device__ __forceinline__ uint32_t tf32u(float x) {
    uint32_t u; asm("cvt.rna.tf32.f32 %0, %1;" : "=r"(u) : "f"(x)); return u;
}
__device__ __forceinline__ void mma_tf32(float d[4], const uint32_t a[4], const uint32_t b[2]) {
    asm volatile(
        "mma.sync.aligned.m16n8k8.row.col.f32.tf32.tf32.f32 "
        "{%0,%1,%2,%3}, {%4,%5,%6,%7}, {%8,%9}, {%0,%1,%2,%3};"
        : "+f"(d[0]), "+f"(d[1]), "+f"(d[2]), "+f"(d[3])
        : "r"(a[0]), "r"(a[1]), "r"(a[2]), "r"(a[3]), "r"(b[0]), "r"(b[1]));
}
__device__ __forceinline__ uint32_t s2u(const void* p) {
    return (uint32_t)__cvta_generic_to_shared(p);
}
__device__ __forceinline__ void cpa16(uint32_t dst, const void* src) {
    asm volatile("cp.async.ca.shared.global [%0], [%1], 16;" :: "r"(dst), "l"(src));
}
__device__ __forceinline__ void cpa_commit() { asm volatile("cp.async.commit_group;"); }
__device__ __forceinline__ void cpa_wait0()  { asm volatile("cp.async.wait_group 0;"); }
__device__ __forceinline__ void cpa_wait1()  { asm volatile("cp.async.wait_group 1;"); }

// ---------------- kernel 0: zero counters ----------------
__global__ void zero_kernel() {
    int t = threadIdx.x;
    if (t < NE) { g_counts[t] = 0; g_imp[t] = 0.f; }
    if (t < NK) g_loadcnt[t] = 0;
}

// ---------------- kernel 1: router + gating + aux stats + scatter ----------------
__global__ void router_kernel(const float* __restrict__ x,
                              const float* __restrict__ rw,
                              const float* __restrict__ rb) {
    __shared__ float xs[HD];
    __shared__ float lg[NE];
    const int s = blockIdx.x;
    const int tid = threadIdx.x;
    const float* xrow = x + (size_t)s * HD;
    for (int i = tid; i < HD / 4; i += 128)
        ((float4*)xs)[i] = ((const float4*)xrow)[i];
    __syncthreads();

    const int w = tid >> 5, lane = tid & 31;
    for (int e = w; e < NE; e += 4) {
        const float* r = rw + (size_t)e * HD;
        float p = 0.f;
        for (int i = lane; i < HD; i += 32) p += xs[i] * r[i];
        #pragma unroll
        for (int o = 16; o; o >>= 1) p += __shfl_xor_sync(0xFFFFFFFFu, p, o);
        if (lane == 0) lg[e] = p + rb[e];
    }
    __syncthreads();

    if (tid == 0) {
        float v[NE];
        #pragma unroll
        for (int e = 0; e < NE; e++) v[e] = lg[e];

        // top-4 (strict >, so ties pick lowest index — matches lax.top_k)
        int idx[NK]; float tv[NK]; bool used[NE];
        #pragma unroll
        for (int e = 0; e < NE; e++) used[e] = false;
        for (int k = 0; k < NK; k++) {
            int bi = 0; float bv = -3.0e38f;
            for (int e = 0; e < NE; e++)
                if (!used[e] && v[e] > bv) { bv = v[e]; bi = e; }
            used[bi] = true; idx[k] = bi; tv[k] = bv;
        }
        // softmax over top-4 values
        float w4[NK], den = 0.f, m = tv[0];
        for (int k = 0; k < NK; k++) { w4[k] = expf(tv[k] - m); den += w4[k]; }
        for (int k = 0; k < NK; k++) w4[k] /= den;

        // full softmax -> importance accumulation
        float mm = v[0];
        for (int e = 1; e < NE; e++) mm = fmaxf(mm, v[e]);
        float pr[NE], d2 = 0.f;
        for (int e = 0; e < NE; e++) { pr[e] = expf(v[e] - mm); d2 += pr[e]; }
        for (int e = 0; e < NE; e++) atomicAdd(&g_imp[e], pr[e] / d2);

        // load = one_hot(argmax over top-k *indices*, E)  (faithful to source)
        int jm = 0;
        for (int k = 1; k < NK; k++) if (idx[k] > idx[jm]) jm = k;
        atomicAdd(&g_loadcnt[jm], 1);

        // scatter token into its 4 expert lists
        for (int k = 0; k < NK; k++) {
            int e = idx[k];
            int slot = atomicAdd(&g_counts[e], 1);
            g_tok[e][slot]  = s;
            g_gate[e][slot] = w4[k];
        }
    }
}

// ---------------- kernel 2: grouped GEMM1 + clip/SiLU fusion ----------------
// act[e, m, f] = silu(clip(x_g @ Win[:, FFD+f] + b_g)) * clip(x_g @ Win[:, f] + b_u)
__global__ void gemm1_kernel(const float* __restrict__ x,
                             const float* __restrict__ Win,
                             const float* __restrict__ bin) {
    extern __shared__ float sm[];
    float* As = sm;                       // [2][64][AST]
    float* Bu = sm + 2 * 64 * AST;        // [2][32][BST]
    float* Bg = Bu + 2 * 32 * BST;        // [2][32][BST]
    __shared__ int toksm[64];

    const int e  = blockIdx.z;
    const int m0 = blockIdx.y * 64;
    const int n0 = blockIdx.x * 64;
    const int cnt = g_counts[e];
    if (m0 >= cnt) return;

    const int tid = threadIdx.x;
    if (tid < 64) {
        int r = m0 + tid;
        toksm[tid] = (r < cnt) ? g_tok[e][r] : 0;
    }
    __syncthreads();

    const uint32_t asb = s2u(As), bub = s2u(Bu), bgb = s2u(Bg);
    const float* Wb = Win + (size_t)e * HD * (2 * FFD);

    const int ar = tid >> 3, ac = (tid & 7) * 4;
    const int br = tid >> 4, bc = (tid & 15) * 4;

    auto issue = [&](int kc, int buf) {
        const int k0 = kc * 32;
        #pragma unroll
        for (int it = 0; it < 4; it++) {
            int r = it * 16 + ar;
            cpa16(asb + (uint32_t)((buf * 64 + r) * AST + ac) * 4,
                  x + (size_t)toksm[r] * HD + k0 + ac);
        }
        #pragma unroll
        for (int it = 0; it < 4; it++) {
            int r = it * 8 + br;
            const float* src = Wb + (size_t)(k0 + r) * (2 * FFD) + n0 + bc;
            cpa16(bub + (uint32_t)((buf * 32 + r) * BST + bc) * 4, src);
            cpa16(bgb + (uint32_t)((buf * 32 + r) * BST + bc) * 4, src + FFD);
        }
        cpa_commit();
    };

    float accU[2][4][4] = {}, accG[2][4][4] = {};
    const int wid = tid >> 5, lane = tid & 31;
    const int wm = wid >> 1, wn = wid & 1;
    const int gq = lane >> 2, tg = lane & 3;

    issue(0, 0);
    const int NKC = HD / 32;
    for (int kc = 0; kc < NKC; kc++) {
        const int buf = kc & 1;
        if (kc + 1 < NKC) { issue(kc + 1, buf ^ 1); cpa_wait1(); }
        else              { cpa_wait0(); }
        __syncthreads();

        const float* Ab  = As + (buf * 64 + wm * 32) * AST;
        const float* Bub = Bu + buf * 32 * BST + wn * 32;
        const float* Bgb = Bg + buf * 32 * BST + wn * 32;
        #pragma unroll
        for (int k8 = 0; k8 < 4; k8++) {
            const int kk = k8 * 8;
            uint32_t a[2][4];
            #pragma unroll
            for (int i = 0; i < 2; i++) {
                const float* ap = Ab + i * 16 * AST;
                a[i][0] = tf32u(ap[(gq    ) * AST + kk + tg    ]);
                a[i][1] = tf32u(ap[(gq + 8) * AST + kk + tg    ]);
                a[i][2] = tf32u(ap[(gq    ) * AST + kk + tg + 4]);
                a[i][3] = tf32u(ap[(gq + 8) * AST + kk + tg + 4]);
            }
            #pragma unroll
            for (int j = 0; j < 4; j++) {
                const int col = j * 8 + gq;
                uint32_t bu[2], bg[2];
                bu[0] = tf32u(Bub[(kk + tg    ) * BST + col]);
                bu[1] = tf32u(Bub[(kk + tg + 4) * BST + col]);
                bg[0] = tf32u(Bgb[(kk + tg    ) * BST + col]);
                bg[1] = tf32u(Bgb[(kk + tg + 4) * BST + col]);
                #pragma unroll
                for (int i = 0; i < 2; i++) {
                    mma_tf32(accU[i][j], a[i], bu);
                    mma_tf32(accG[i][j], a[i], bg);
                }
            }
        }
        __syncthreads();
    }

    // epilogue: bias + clip + SiLU, write act
    const int mlim = cnt - m0;
    const float* binU = bin + (size_t)e * 2 * FFD + n0;
    const float* binG = binU + FFD;
    #pragma unroll
    for (int i = 0; i < 2; i++) {
        #pragma unroll
        for (int j = 0; j < 4; j++) {
            #pragma unroll
            for (int q = 0; q < 4; q++) {
                const int r = wm * 32 + i * 16 + gq + ((q >= 2) ? 8 : 0);
                const int c = wn * 32 + j * 8 + tg * 2 + (q & 1);
                if (r < mlim) {
                    float up = accU[i][j][q] + binU[c];
                    float gt = accG[i][j][q] + binG[c];
                    up = fminf(fmaxf(up, -7.0f), 7.0f);
                    gt = fminf(fmaxf(gt, -7.0f), 7.0f);
                    float act = (gt / (1.0f + expf(-gt))) * up;
                    g_act[(size_t)(e * TS + m0 + r) * FFD + n0 + c] = act;
                }
            }
        }
    }
}

// ---------------- kernel 3: grouped GEMM2 + weighted scatter-add ----------------
__global__ void gemm2_kernel(const float* __restrict__ Wout,
                             const float* __restrict__ bout,
                             float* __restrict__ out) {
    __shared__ float As[2][64][AST];
    __shared__ float Bs[2][32][BST];
    __shared__ int   toksm[64];
    __shared__ float gsm[64];

    const int e  = blockIdx.z;
    const int m0 = blockIdx.y * 64;
    const int n0 = blockIdx.x * 64;
    const int cnt = g_counts[e];
    if (m0 >= cnt) return;

    const int tid = threadIdx.x;
    if (tid < 64) {
        int r = m0 + tid;
        toksm[tid] = (r < cnt) ? g_tok[e][r] : 0;
        gsm[tid]   = (r < cnt) ? g_gate[e][r] : 0.f;
    }
    __syncthreads();

    const uint32_t asb = s2u(As), bsb = s2u(Bs);
    const float* Wb   = Wout + (size_t)e * FFD * HD;
    const float* Arow = g_act + (size_t)(e * TS + m0) * FFD;

    const int ar = tid >> 3, ac = (tid & 7) * 4;
    const int br = tid >> 4, bc = (tid & 15) * 4;

    auto issue = [&](int kc, int buf) {
        const int k0 = kc * 32;
        #pragma unroll
        for (int it = 0; it < 4; it++) {
            int r = it * 16 + ar;
            cpa16(asb + (uint32_t)((buf * 64 + r) * AST + ac) * 4,
                  Arow + (size_t)r * FFD + k0 + ac);
        }
        #pragma unroll
        for (int it = 0; it < 4; it++) {
            int r = it * 8 + br;
            cpa16(bsb + (uint32_t)((buf * 32 + r) * BST + bc) * 4,
                  Wb + (size_t)(k0 + r) * HD + n0 + bc);
        }
        cpa_commit();
    };

    float acc[2][4][4] = {};
    const int wid = tid >> 5, lane = tid & 31;
    const int wm = wid >> 1, wn = wid & 1;
    const int gq = lane >> 2, tg = lane & 3;

    issue(0, 0);
    const int NKC = FFD / 32;
    for (int kc = 0; kc < NKC; kc++) {
        const int buf = kc & 1;
        if (kc + 1 < NKC) { issue(kc + 1, buf ^ 1); cpa_wait1(); }
        else              { cpa_wait0(); }
        __syncthreads();

        const float* Ab = &As[buf][wm * 32][0];
        const float* Bb = &Bs[buf][0][wn * 32];
        #pragma unroll
        for (int k8 = 0; k8 < 4; k8++) {
            const int kk = k8 * 8;
            uint32_t a[2][4];
            #pragma unroll
            for (int i = 0; i < 2; i++) {
                const float* ap = Ab + i * 16 * AST;
                a[i][0] = tf32u(ap[(gq    ) * AST + kk + tg    ]);
                a[i][1] = tf32u(ap[(gq + 8) * AST + kk + tg    ]);
                a[i][2] = tf32u(ap[(gq    ) * AST + kk + tg + 4]);
                a[i][3] = tf32u(ap[(gq + 8) * AST + kk + tg + 4]);
            }
            #pragma unroll
            for (int j = 0; j < 4; j++) {
                const int col = j * 8 + gq;
                uint32_t b[2];
                b[0] = tf32u(Bb[(kk + tg    ) * BST + col]);
                b[1] = tf32u(Bb[(kk + tg + 4) * BST + col]);
                #pragma unroll
                for (int i = 0; i < 2; i++)
                    mma_tf32(acc[i][j], a[i], b);
            }
        }
        __syncthreads();
    }

    const int mlim = cnt - m0;
    const float* bo = bout + (size_t)e * HD + n0;
    #pragma unroll
    for (int i = 0; i < 2; i++) {
        #pragma unroll
        for (int j = 0; j < 4; j++) {
            #pragma unroll
            for (int q = 0; q < 4; q++) {
                const int r = wm * 32 + i * 16 + gq + ((q >= 2) ? 8 : 0);
                const int c = wn * 32 + j * 8 + tg * 2 + (q & 1);
                if (r < mlim) {
                    float val = acc[i][j][q] + bo[c];
                    atomicAdd(&out[(size_t)toksm[r] * HD + n0 + c], gsm[r] * val);
                }
            }
        }
    }
}

// ---------------- kernel 4: aux loss scalar ----------------
__global__ void aux_kernel(float* __restrict__ out, int out_size) {
    if (out_size > TS * HD) {
        float a = 0.f;
        #pragma unroll
        for (int j = 0; j < NK; j++)
            a += (g_imp[j] / (float)TS) * ((float)g_loadcnt[j] / (float)TS);
        out[TS * HD] = 0.02f * (float)NE * a;
    }
}

// ---------------- launcher ----------------
extern "C" void kernel_launch(void* const* d_in, const int* in_sizes, int n_in,
                              void* d_out, int out_size) {
    const float* x    = (const float*)d_in[0];
    const float* Win  = (const float*)d_in[1];
    const float* bin  = (const float*)d_in[2];
    const float* Wout = (const float*)d_in[3];
    const float* bout = (const float*)d_in[4];
    const float* rw   = (const float*)d_in[5];
    const float* rb   = (const float*)d_in[6];
    float* out = (float*)d_out;

    const int g1_smem = (2 * 64 * AST + 2 * 2 * 32 * BST) * 4;  // 55296 B
    cudaFuncSetAttribute(gemm1_kernel, cudaFuncAttributeMaxDynamicSharedMemorySize, g1_smem);

    cudaMemsetAsync(d_out, 0, (size_t)out_size * sizeof(float));
    zero_kernel<<<1, 32>>>();
    router_kernel<<<TS, 128>>>(x, rw, rb);
    gemm1_kernel<<<dim3(FFD / 64, TS / 64, NE), 128, g1_smem>>>(x, Win, bin);
    gemm2_kernel<<<dim3(HD / 64, TS / 64, NE), 128>>>(Wout, bout, out);
    aux_kernel<<<1, 1>>>(out, out_size);
}